// round 6
// baseline (speedup 1.0000x reference)
#include <cuda_runtime.h>
#include <cuda.h>
#include <cuda_fp16.h>
#include <cstdint>
#include <math.h>

// Problem dims (fixed by the dataset)
#define B_ 4
#define S_ 4096
#define D_ 2048
#define DI_ 8192
#define MTOT (B_ * S_)   // 16384

// ---------------------------------------------------------------------------
// Static device scratch
// ---------------------------------------------------------------------------
__device__ __half g_xh[(size_t)MTOT * D_];    //  64 MB  x in fp16
__device__ __half g_wuph[(size_t)DI_ * D_];   //  32 MB  w_up fp16 [DI, D] K-major
__device__ __half g_wdh[(size_t)D_ * DI_];    //  32 MB  w_down fp16 [D, DI] K-major
__device__ __half g_h[(size_t)MTOT * DI_];    // 256 MB  gelu(up) intermediate

// ---------------------------------------------------------------------------
// GEMM config: CTA 128x128, 4 warps (2M x 2N), warp tile 64x64, BK=64,
// 3 stages (96 KB), 2 CTAs/SM. TMA tile loads + mbarrier; fragment
// double-buffered LDSM/MMA mainloop.
// ---------------------------------------------------------------------------
constexpr int BM = 128;
constexpr int BN = 128;
constexpr int BK = 64;                            // 64 halfs = 128 B per row
constexpr int STAGES = 3;
constexpr int NTHREADS = 128;
constexpr int A_BYTES = BM * 128;                 // 16 KB
constexpr int B_BYTES = BN * 128;                 // 16 KB
constexpr int STAGE_BYTES = A_BYTES + B_BYTES;    // 32 KB
constexpr int SMEM_BYTES = STAGES * STAGE_BYTES + 1024;  // + align pad
constexpr uint32_t STAGE_TX = STAGE_BYTES;        // expected TMA bytes / stage

// ---------------------------------------------------------------------------
// PTX helpers
// ---------------------------------------------------------------------------
__device__ __forceinline__ uint32_t smem_u32(const void* p) {
    return (uint32_t)__cvta_generic_to_shared(p);
}
__device__ __forceinline__ void ldsm_x4(uint32_t& r0, uint32_t& r1, uint32_t& r2,
                                        uint32_t& r3, uint32_t addr) {
    asm volatile("ldmatrix.sync.aligned.m8n8.x4.shared.b16 {%0,%1,%2,%3}, [%4];\n"
                 : "=r"(r0), "=r"(r1), "=r"(r2), "=r"(r3) : "r"(addr));
}
__device__ __forceinline__ void mma16816(float* d, const uint32_t* a, const uint32_t* b) {
    asm volatile(
        "mma.sync.aligned.m16n8k16.row.col.f32.f16.f16.f32 "
        "{%0,%1,%2,%3}, {%4,%5,%6,%7}, {%8,%9}, {%0,%1,%2,%3};\n"
        : "+f"(d[0]), "+f"(d[1]), "+f"(d[2]), "+f"(d[3])
        : "r"(a[0]), "r"(a[1]), "r"(a[2]), "r"(a[3]), "r"(b[0]), "r"(b[1]));
}
__device__ __forceinline__ void mbar_init(uint32_t mbar, uint32_t cnt) {
    asm volatile("mbarrier.init.shared.b64 [%0], %1;" :: "r"(mbar), "r"(cnt) : "memory");
}
__device__ __forceinline__ void mbar_expect_tx(uint32_t mbar, uint32_t bytes) {
    asm volatile("mbarrier.arrive.expect_tx.shared.b64 _, [%0], %1;"
                 :: "r"(mbar), "r"(bytes) : "memory");
}
__device__ __forceinline__ void mbar_wait(uint32_t mbar, int phase) {
    asm volatile(
        "{\n\t"
        ".reg .pred P1;\n\t"
        "WL_%=:\n\t"
        "mbarrier.try_wait.parity.acquire.cta.shared::cta.b64 P1, [%0], %1, 0x989680;\n\t"
        "@P1 bra.uni WD_%=;\n\t"
        "bra.uni WL_%=;\n\t"
        "WD_%=:\n\t"
        "}"
        :: "r"(mbar), "r"(phase) : "memory");
}
__device__ __forceinline__ void tma_load_2d(uint32_t dst, const CUtensorMap* map,
                                            int x, int y, uint32_t mbar) {
    asm volatile(
        "cp.async.bulk.tensor.2d.shared::cta.global.tile.mbarrier::complete_tx::bytes "
        "[%0], [%1, {%2, %3}], [%4];"
        :: "r"(dst), "l"(map), "r"(x), "r"(y), "r"(mbar) : "memory");
}
__device__ __forceinline__ float gelu_exact(float v) {
    return 0.5f * v * (1.0f + erff(v * 0.70710678118654752f));
}

// ---------------------------------------------------------------------------
// Conversion kernels
// ---------------------------------------------------------------------------
__global__ void cvt_x_kernel(const float* __restrict__ in) {
    int i = blockIdx.x * blockDim.x + threadIdx.x;
    float4 v = reinterpret_cast<const float4*>(in)[i];
    __half2* o = reinterpret_cast<__half2*>(g_xh);
    o[2 * i]     = __floats2half2_rn(v.x, v.y);
    o[2 * i + 1] = __floats2half2_rn(v.z, v.w);
}
__global__ void cvt_wup_kernel(const float* __restrict__ in) {
    int i = blockIdx.x * blockDim.x + threadIdx.x;
    float4 v = reinterpret_cast<const float4*>(in)[i];
    __half2* o = reinterpret_cast<__half2*>(g_wuph);
    o[2 * i]     = __floats2half2_rn(v.x, v.y);
    o[2 * i + 1] = __floats2half2_rn(v.z, v.w);
}
__global__ void cvt_wd_kernel(const int* __restrict__ in) {
    int i = blockIdx.x * blockDim.x + threadIdx.x;
    int4 v = reinterpret_cast<const int4*>(in)[i];
    __half2* o = reinterpret_cast<__half2*>(g_wdh);
    o[2 * i]     = __floats2half2_rn((float)v.x, (float)v.y);
    o[2 * i + 1] = __floats2half2_rn((float)v.z, (float)v.w);
}

// ---------------------------------------------------------------------------
// Tiled fp16 GEMM, TMA-fed, fused epilogue.
//   GEMM1:  g_h  = gelu( A[M,K] @ B[N,K]^T + bias )        (K=D, N=DI)
//   GEMM2:  out  = ( A[M,K] @ B[N,K]^T ) * scale + bias    (K=DI, N=D)
// SMEM per stage: A tile [128 rows x 128 B] then B tile, SW128 swizzled
// (TMA SW128 == chunk c of row r at (c ^ (r & 7)) in 16B units).
// ---------------------------------------------------------------------------
template <int KDIM, int NDIM, bool IS_GEMM1>
__global__ void __launch_bounds__(NTHREADS, 2)
ffn_gemm_tma(const __grid_constant__ CUtensorMap tmA,
             const __grid_constant__ CUtensorMap tmB,
             const float* __restrict__ bias,
             const float* __restrict__ scale,
             float* __restrict__ outp)
{
    extern __shared__ char dyn_raw[];
    char* dsm = (char*)((((uintptr_t)dyn_raw) + 1023) & ~(uintptr_t)1023);
    __shared__ alignas(8) uint64_t mbar[STAGES];

    const int m0 = blockIdx.y * BM;
    const int n0 = blockIdx.x * BN;
    const int tid = threadIdx.x;
    const int wid = tid >> 5;
    const int lane = tid & 31;
    const int wm = (wid & 1) * 64;
    const int wn = (wid >> 1) * 64;

    float acc[4][8][4];
#pragma unroll
    for (int mt = 0; mt < 4; ++mt)
#pragma unroll
        for (int nt = 0; nt < 8; ++nt)
#pragma unroll
            for (int i = 0; i < 4; ++i) acc[mt][nt][i] = 0.0f;

    constexpr int KTILES = KDIM / BK;

    // Fixed per-thread LDSM indices
    const int rowA0 = wm + (lane & 15);
    const int rowB0 = wn + ((lane >> 4) << 3) + (lane & 7);
    const int cA = (lane >> 4);
    const int cB = ((lane >> 3) & 1);

    if (tid == 0) {
#pragma unroll
        for (int s = 0; s < STAGES; ++s) mbar_init(smem_u32(&mbar[s]), 1);
    }
    __syncthreads();

    auto issue_stage = [&](int s, int kt) {
        uint32_t aDst = smem_u32(dsm + s * STAGE_BYTES);
        uint32_t bDst = aDst + A_BYTES;
        uint32_t bar = smem_u32(&mbar[s]);
        mbar_expect_tx(bar, STAGE_TX);
        tma_load_2d(aDst, &tmA, kt * BK, m0, bar);
        tma_load_2d(bDst, &tmB, kt * BK, n0, bar);
    };

    // Prologue: issue STAGES-1 stages
    if (tid == 0) {
#pragma unroll
        for (int s = 0; s < STAGES - 1; ++s) issue_stage(s, s);
    }

    int ph[STAGES];
#pragma unroll
    for (int s = 0; s < STAGES; ++s) ph[s] = 0;

    uint32_t fA[2][4][4];
    uint32_t fB[2][4][4];

    auto ldsm_kk = [&](const uint4* Aa, const uint4* Ba, int kk, int buf) {
#pragma unroll
        for (int mt = 0; mt < 4; ++mt) {
            int row = rowA0 + mt * 16;
            int c = kk * 2 + cA;
            ldsm_x4(fA[buf][mt][0], fA[buf][mt][1], fA[buf][mt][2], fA[buf][mt][3],
                    smem_u32(Aa + row * 8 + (c ^ (row & 7))));
        }
#pragma unroll
        for (int nt2 = 0; nt2 < 4; ++nt2) {
            int row = rowB0 + nt2 * 16;
            int c = kk * 2 + cB;
            ldsm_x4(fB[buf][nt2][0], fB[buf][nt2][1], fB[buf][nt2][2], fB[buf][nt2][3],
                    smem_u32(Ba + row * 8 + (c ^ (row & 7))));
        }
    };

    auto mma_kk = [&](int buf) {
#pragma unroll
        for (int mt = 0; mt < 4; ++mt)
#pragma unroll
            for (int nt = 0; nt < 8; ++nt)
                mma16816(acc[mt][nt], fA[buf][mt], &fB[buf][nt >> 1][(nt & 1) * 2]);
    };

    for (int kt = 0; kt < KTILES; ++kt) {
        const int st = kt % STAGES;

        // All warps done reading the stage about to be overwritten.
        __syncthreads();
        if (tid == 0) {
            int ls = kt + STAGES - 1;
            if (ls < KTILES) issue_stage(ls % STAGES, ls);
        }

        mbar_wait(smem_u32(&mbar[st]), ph[st]);
        ph[st] ^= 1;

        const uint4* Aa = (const uint4*)(dsm + st * STAGE_BYTES);
        const uint4* Ba = (const uint4*)(dsm + st * STAGE_BYTES + A_BYTES);

        ldsm_kk(Aa, Ba, 0, 0);
#pragma unroll
        for (int kk = 0; kk < BK / 16; ++kk) {
            if (kk + 1 < BK / 16) ldsm_kk(Aa, Ba, kk + 1, (kk + 1) & 1);
            mma_kk(kk & 1);
        }
    }

    // ------------------------------------------------------------------ epilogue
    const int r0g = m0 + wm + (lane >> 2);
    const int c0g = n0 + wn + ((lane & 3) << 1);

    if (IS_GEMM1) {
#pragma unroll
        for (int mt = 0; mt < 4; ++mt)
#pragma unroll
            for (int hrow = 0; hrow < 2; ++hrow) {
                int row = r0g + mt * 16 + hrow * 8;
#pragma unroll
                for (int nt = 0; nt < 8; ++nt) {
                    int col = c0g + nt * 8;
                    float v0 = acc[mt][nt][hrow * 2]     + bias[col];
                    float v1 = acc[mt][nt][hrow * 2 + 1] + bias[col + 1];
                    v0 = gelu_exact(v0);
                    v1 = gelu_exact(v1);
                    *reinterpret_cast<__half2*>(&g_h[(size_t)row * NDIM + col]) =
                        __floats2half2_rn(v0, v1);
                }
            }
    } else {
#pragma unroll
        for (int mt = 0; mt < 4; ++mt)
#pragma unroll
            for (int hrow = 0; hrow < 2; ++hrow) {
                int row = r0g + mt * 16 + hrow * 8;
#pragma unroll
                for (int nt = 0; nt < 8; ++nt) {
                    int col = c0g + nt * 8;
                    float2 o;
                    o.x = acc[mt][nt][hrow * 2]     * scale[col]     + bias[col];
                    o.y = acc[mt][nt][hrow * 2 + 1] * scale[col + 1] + bias[col + 1];
                    *reinterpret_cast<float2*>(&outp[(size_t)row * NDIM + col]) = o;
                }
            }
    }
}

// ---------------------------------------------------------------------------
// Host: tensor-map construction (driver entry point, no -lcuda needed)
// ---------------------------------------------------------------------------
typedef CUresult (*EncodeFn)(CUtensorMap*, CUtensorMapDataType, cuuint32_t, void*,
                             const cuuint64_t*, const cuuint64_t*, const cuuint32_t*,
                             const cuuint32_t*, CUtensorMapInterleave, CUtensorMapSwizzle,
                             CUtensorMapL2promotion, CUtensorMapFloatOOBfill);

static void make_map(EncodeFn fn, CUtensorMap* m, void* base,
                     uint64_t rows, uint64_t kdim, uint32_t box_rows) {
    cuuint64_t dims[2] = {kdim, rows};
    cuuint64_t strides[1] = {kdim * 2};       // bytes between rows
    cuuint32_t box[2] = {64, box_rows};       // 64 halfs = 128 B (SW128 atom)
    cuuint32_t es[2] = {1, 1};
    fn(m, CU_TENSOR_MAP_DATA_TYPE_FLOAT16, 2, base, dims, strides, box, es,
       CU_TENSOR_MAP_INTERLEAVE_NONE, CU_TENSOR_MAP_SWIZZLE_128B,
       CU_TENSOR_MAP_L2_PROMOTION_L2_128B, CU_TENSOR_MAP_FLOAT_OOB_FILL_NONE);
}

extern "C" void kernel_launch(void* const* d_in, const int* in_sizes, int n_in,
                              void* d_out, int out_size)
{
    const float* x            = (const float*)d_in[0];  // [B,S,D]
    const float* w_up         = (const float*)d_in[1];  // [DI,D]
    const float* b_up         = (const float*)d_in[2];  // [DI]
    const int*   w_down_q     = (const int*)  d_in[3];  // [D,DI] int32
    const float* w_down_scale = (const float*)d_in[4];  // [D]
    const float* b_down       = (const float*)d_in[5];  // [D]
    float* out = (float*)d_out;                         // [B,S,D]

    cvt_x_kernel  <<<(MTOT * D_) / 4 / 256, 256>>>(x);
    cvt_wup_kernel<<<(DI_ * D_) / 4 / 256, 256>>>(w_up);
    cvt_wd_kernel <<<(D_ * DI_) / 4 / 256, 256>>>(w_down_q);

    // Tensor maps (host-side, capture-safe)
    void* fnp = nullptr;
    cudaDriverEntryPointQueryResult qr;
    cudaGetDriverEntryPoint("cuTensorMapEncodeTiled", &fnp, cudaEnableDefault, &qr);
    EncodeFn enc = (EncodeFn)fnp;

    void *pxh, *pwup, *pwd, *phh;
    cudaGetSymbolAddress(&pxh, g_xh);
    cudaGetSymbolAddress(&pwup, g_wuph);
    cudaGetSymbolAddress(&pwd, g_wdh);
    cudaGetSymbolAddress(&phh, g_h);

    CUtensorMap tA1, tB1, tA2, tB2;
    make_map(enc, &tA1, pxh,  MTOT, D_,  BM);
    make_map(enc, &tB1, pwup, DI_,  D_,  BN);
    make_map(enc, &tA2, phh,  MTOT, DI_, BM);
    make_map(enc, &tB2, pwd,  D_,   DI_, BN);

    cudaFuncSetAttribute(ffn_gemm_tma<D_, DI_, true>,
                         cudaFuncAttributeMaxDynamicSharedMemorySize, SMEM_BYTES);
    ffn_gemm_tma<D_, DI_, true>
        <<<dim3(DI_ / BN, MTOT / BM), NTHREADS, SMEM_BYTES>>>(tA1, tB1, b_up, nullptr, nullptr);

    cudaFuncSetAttribute(ffn_gemm_tma<DI_, D_, false>,
                         cudaFuncAttributeMaxDynamicSharedMemorySize, SMEM_BYTES);
    ffn_gemm_tma<DI_, D_, false>
        <<<dim3(D_ / BN, MTOT / BM), NTHREADS, SMEM_BYTES>>>(tA2, tB2, b_down, w_down_scale, out);
}

// round 8
// speedup vs baseline: 1.1219x; 1.1219x over previous
#include <cuda_runtime.h>
#include <cuda_fp16.h>
#include <cstdint>
#include <math.h>

// Problem dims (fixed by the dataset)
#define B_ 4
#define S_ 4096
#define D_ 2048
#define DI_ 8192
#define MTOT (B_ * S_)   // 16384

// ---------------------------------------------------------------------------
// Static device scratch
// ---------------------------------------------------------------------------
__device__ __half g_xh[(size_t)MTOT * D_];    //  64 MB  x in fp16
__device__ __half g_wuph[(size_t)DI_ * D_];   //  32 MB  w_up fp16 [DI, D] K-major
__device__ __half g_wdh[(size_t)D_ * DI_];    //  32 MB  w_down fp16 [D, DI] K-major
__device__ __half g_h[(size_t)MTOT * DI_];    // 256 MB  gelu(up) intermediate

// ---------------------------------------------------------------------------
// GEMM config: CTA 128x128, 4 warps (2M x 2N), warp tile 64x64, BK=64,
// 3 stages (96 KB), 2 CTAs/SM. Fragment double buffering + cross-tile
// ldsm prefetch (barrier-published cp.async completeness).
// ---------------------------------------------------------------------------
constexpr int BM = 128;
constexpr int BN = 128;
constexpr int BK = 64;
constexpr int STAGES = 3;
constexpr int NTHREADS = 128;
constexpr int A_CHUNKS = BM * 8;
constexpr int B_CHUNKS = BN * 8;
constexpr int STAGE_BYTES = (BM + BN) * 128;     // 32 KB
constexpr int SMEM_BYTES = STAGES * STAGE_BYTES; // 96 KB

// ---------------------------------------------------------------------------
// PTX helpers
// ---------------------------------------------------------------------------
__device__ __forceinline__ uint32_t smem_u32(const void* p) {
    return (uint32_t)__cvta_generic_to_shared(p);
}
__device__ __forceinline__ void cp_async16(uint32_t dst, const void* src) {
    asm volatile("cp.async.cg.shared.global [%0], [%1], 16;\n"
                 :: "r"(dst), "l"(src) : "memory");
}
__device__ __forceinline__ void cp_commit() {
    asm volatile("cp.async.commit_group;\n" ::: "memory");
}
template <int N>
__device__ __forceinline__ void cp_wait() {
    asm volatile("cp.async.wait_group %0;\n" :: "n"(N) : "memory");
}
__device__ __forceinline__ void ldsm_x4(uint32_t& r0, uint32_t& r1, uint32_t& r2,
                                        uint32_t& r3, uint32_t addr) {
    asm volatile("ldmatrix.sync.aligned.m8n8.x4.shared.b16 {%0,%1,%2,%3}, [%4];\n"
                 : "=r"(r0), "=r"(r1), "=r"(r2), "=r"(r3) : "r"(addr));
}
__device__ __forceinline__ void mma16816(float* d, const uint32_t* a, const uint32_t* b) {
    asm volatile(
        "mma.sync.aligned.m16n8k16.row.col.f32.f16.f16.f32 "
        "{%0,%1,%2,%3}, {%4,%5,%6,%7}, {%8,%9}, {%0,%1,%2,%3};\n"
        : "+f"(d[0]), "+f"(d[1]), "+f"(d[2]), "+f"(d[3])
        : "r"(a[0]), "r"(a[1]), "r"(a[2]), "r"(a[3]), "r"(b[0]), "r"(b[1]));
}
__device__ __forceinline__ float gelu_exact(float v) {
    return 0.5f * v * (1.0f + erff(v * 0.70710678118654752f));
}

// ---------------------------------------------------------------------------
// Conversion kernels
// ---------------------------------------------------------------------------
__global__ void cvt_x_kernel(const float* __restrict__ in) {
    int i = blockIdx.x * blockDim.x + threadIdx.x;
    float4 v = reinterpret_cast<const float4*>(in)[i];
    __half2* o = reinterpret_cast<__half2*>(g_xh);
    o[2 * i]     = __floats2half2_rn(v.x, v.y);
    o[2 * i + 1] = __floats2half2_rn(v.z, v.w);
}
__global__ void cvt_wup_kernel(const float* __restrict__ in) {
    int i = blockIdx.x * blockDim.x + threadIdx.x;
    float4 v = reinterpret_cast<const float4*>(in)[i];
    __half2* o = reinterpret_cast<__half2*>(g_wuph);
    o[2 * i]     = __floats2half2_rn(v.x, v.y);
    o[2 * i + 1] = __floats2half2_rn(v.z, v.w);
}
__global__ void cvt_wd_kernel(const int* __restrict__ in) {
    int i = blockIdx.x * blockDim.x + threadIdx.x;
    int4 v = reinterpret_cast<const int4*>(in)[i];
    __half2* o = reinterpret_cast<__half2*>(g_wdh);
    o[2 * i]     = __floats2half2_rn((float)v.x, (float)v.y);
    o[2 * i + 1] = __floats2half2_rn((float)v.z, (float)v.w);
}

// ---------------------------------------------------------------------------
// Tiled fp16 GEMM, fused epilogue, cross-tile pipelined mainloop.
//   Tile body:  loads(kt+2); ldsm1/mma0; ldsm2/mma1; ldsm3/mma2;
//               cp_wait; BAR; ldsm0'(kt+1); mma3.
//   The barrier publishes ALL threads' stage-(kt+1) cp.async completions,
//   making the post-bar prefetch race-free; mma3 needs no new data, so the
//   tensor pipe resumes immediately after the barrier.
// ---------------------------------------------------------------------------
template <int KDIM, int NDIM, bool IS_GEMM1>
__global__ void __launch_bounds__(NTHREADS, 2)
ffn_gemm_kernel(const float* __restrict__ bias,
                const float* __restrict__ scale,
                float* __restrict__ outp)
{
    extern __shared__ uint4 smem[];   // [STAGES][(BM+BN)*8] 16B chunks

    const __half* Ag = IS_GEMM1 ? g_xh   : g_h;
    const __half* Bg = IS_GEMM1 ? g_wuph : g_wdh;

    const int m0 = blockIdx.y * BM;
    const int n0 = blockIdx.x * BN;
    const int tid = threadIdx.x;
    const int wid = tid >> 5;
    const int lane = tid & 31;
    const int wm = (wid & 1) * 64;
    const int wn = (wid >> 1) * 64;

    float acc[4][8][4];
#pragma unroll
    for (int mt = 0; mt < 4; ++mt)
#pragma unroll
        for (int nt = 0; nt < 8; ++nt)
#pragma unroll
            for (int i = 0; i < 4; ++i) acc[mt][nt][i] = 0.0f;

    constexpr int KTILES = KDIM / BK;

    const int rowA0 = wm + (lane & 15);
    const int rowB0 = wn + ((lane >> 4) << 3) + (lane & 7);
    const int cA = (lane >> 4);
    const int cB = ((lane >> 3) & 1);

    auto load_stage = [&](int s, int kt) {
        const __half* aBase = Ag + (size_t)m0 * KDIM + kt * BK;
        const __half* bBase = Bg + (size_t)n0 * KDIM + kt * BK;
        uint4* Ad = smem + s * (A_CHUNKS + B_CHUNKS);
        uint4* Bd = Ad + A_CHUNKS;
#pragma unroll
        for (int i = 0; i < A_CHUNKS / NTHREADS; ++i) {
            int idx = tid + i * NTHREADS;
            int r = idx >> 3, c = idx & 7;
            cp_async16(smem_u32(Ad + r * 8 + (c ^ (r & 7))),
                       aBase + (size_t)r * KDIM + c * 8);
        }
#pragma unroll
        for (int i = 0; i < B_CHUNKS / NTHREADS; ++i) {
            int idx = tid + i * NTHREADS;
            int r = idx >> 3, c = idx & 7;
            cp_async16(smem_u32(Bd + r * 8 + (c ^ (r & 7))),
                       bBase + (size_t)r * KDIM + c * 8);
        }
    };

    uint32_t fA[2][4][4];
    uint32_t fB[2][4][4];

    auto ldsm_kk = [&](const uint4* Aa, const uint4* Ba, int kk, int buf) {
#pragma unroll
        for (int mt = 0; mt < 4; ++mt) {
            int row = rowA0 + mt * 16;
            int c = kk * 2 + cA;
            ldsm_x4(fA[buf][mt][0], fA[buf][mt][1], fA[buf][mt][2], fA[buf][mt][3],
                    smem_u32(Aa + row * 8 + (c ^ (row & 7))));
        }
#pragma unroll
        for (int nt2 = 0; nt2 < 4; ++nt2) {
            int row = rowB0 + nt2 * 16;
            int c = kk * 2 + cB;
            ldsm_x4(fB[buf][nt2][0], fB[buf][nt2][1], fB[buf][nt2][2], fB[buf][nt2][3],
                    smem_u32(Ba + row * 8 + (c ^ (row & 7))));
        }
    };

    auto mma_kk = [&](int buf) {
#pragma unroll
        for (int mt = 0; mt < 4; ++mt)
#pragma unroll
            for (int nt = 0; nt < 8; ++nt)
                mma16816(acc[mt][nt], fA[buf][mt], &fB[buf][nt >> 1][(nt & 1) * 2]);
    };

    // Prologue: fill STAGES-1 stages, then prime kk=0 fragments of tile 0.
#pragma unroll
    for (int s = 0; s < STAGES - 1; ++s) {
        load_stage(s, s);
        cp_commit();
    }
    cp_wait<STAGES - 2>();   // own stage-0 group done
    __syncthreads();         // publishes ALL threads' stage-0 data
    ldsm_kk(smem, smem + A_CHUNKS, 0, 0);

    for (int kt = 0; kt < KTILES; ++kt) {
        const uint4* Aa = smem + (kt % STAGES) * (A_CHUNKS + B_CHUNKS);
        const uint4* Ba = Aa + A_CHUNKS;

        // Refill stage kt+2 (buffer freed by the barrier at end of tile kt-1).
        int ls = kt + STAGES - 1;
        if (ls < KTILES) load_stage(ls % STAGES, ls);
        cp_commit();   // unconditional: uniform group count

        ldsm_kk(Aa, Ba, 1, 1); mma_kk(0);
        ldsm_kk(Aa, Ba, 2, 0); mma_kk(1);
        ldsm_kk(Aa, Ba, 3, 1); mma_kk(0);

        // End-of-tile sync moved BEFORE the last MMA burst:
        cp_wait<STAGES - 2>();   // own stage-(kt+1) group done
        __syncthreads();         // all threads' stage-(kt+1) data published;
                                 // also frees buffer (kt+2)%STAGES for next refill
        if (kt + 1 < KTILES) {
            const uint4* An = smem + ((kt + 1) % STAGES) * (A_CHUNKS + B_CHUNKS);
            ldsm_kk(An, An + A_CHUNKS, 0, 0);   // prefetch next tile kk=0
        }
        mma_kk(1);               // independent of the prefetch -> no pipe gap
    }

    // ------------------------------------------------------------------ epilogue
    const int r0g = m0 + wm + (lane >> 2);
    const int c0g = n0 + wn + ((lane & 3) << 1);

    if (IS_GEMM1) {
#pragma unroll
        for (int mt = 0; mt < 4; ++mt)
#pragma unroll
            for (int hrow = 0; hrow < 2; ++hrow) {
                int row = r0g + mt * 16 + hrow * 8;
#pragma unroll
                for (int nt = 0; nt < 8; ++nt) {
                    int col = c0g + nt * 8;
                    float v0 = acc[mt][nt][hrow * 2]     + bias[col];
                    float v1 = acc[mt][nt][hrow * 2 + 1] + bias[col + 1];
                    v0 = gelu_exact(v0);
                    v1 = gelu_exact(v1);
                    *reinterpret_cast<__half2*>(&g_h[(size_t)row * NDIM + col]) =
                        __floats2half2_rn(v0, v1);
                }
            }
    } else {
#pragma unroll
        for (int mt = 0; mt < 4; ++mt)
#pragma unroll
            for (int hrow = 0; hrow < 2; ++hrow) {
                int row = r0g + mt * 16 + hrow * 8;
#pragma unroll
                for (int nt = 0; nt < 8; ++nt) {
                    int col = c0g + nt * 8;
                    float2 o;
                    o.x = acc[mt][nt][hrow * 2]     * scale[col]     + bias[col];
                    o.y = acc[mt][nt][hrow * 2 + 1] * scale[col + 1] + bias[col + 1];
                    *reinterpret_cast<float2*>(&outp[(size_t)row * NDIM + col]) = o;
                }
            }
    }
}

// ---------------------------------------------------------------------------
// Launch
// ---------------------------------------------------------------------------
extern "C" void kernel_launch(void* const* d_in, const int* in_sizes, int n_in,
                              void* d_out, int out_size)
{
    const float* x            = (const float*)d_in[0];  // [B,S,D]
    const float* w_up         = (const float*)d_in[1];  // [DI,D]
    const float* b_up         = (const float*)d_in[2];  // [DI]
    const int*   w_down_q     = (const int*)  d_in[3];  // [D,DI] int32
    const float* w_down_scale = (const float*)d_in[4];  // [D]
    const float* b_down       = (const float*)d_in[5];  // [D]
    float* out = (float*)d_out;                         // [B,S,D]

    cvt_x_kernel  <<<(MTOT * D_) / 4 / 256, 256>>>(x);
    cvt_wup_kernel<<<(DI_ * D_) / 4 / 256, 256>>>(w_up);
    cvt_wd_kernel <<<(D_ * DI_) / 4 / 256, 256>>>(w_down_q);

    cudaFuncSetAttribute(ffn_gemm_kernel<D_, DI_, true>,
                         cudaFuncAttributeMaxDynamicSharedMemorySize, SMEM_BYTES);
    ffn_gemm_kernel<D_, DI_, true>
        <<<dim3(DI_ / BN, MTOT / BM), NTHREADS, SMEM_BYTES>>>(b_up, nullptr, nullptr);

    cudaFuncSetAttribute(ffn_gemm_kernel<DI_, D_, false>,
                         cudaFuncAttributeMaxDynamicSharedMemorySize, SMEM_BYTES);
    ffn_gemm_kernel<DI_, D_, false>
        <<<dim3(D_ / BN, MTOT / BM), NTHREADS, SMEM_BYTES>>>(b_down, w_down_scale, out);
}